// round 5
// baseline (speedup 1.0000x reference)
#include <cuda_runtime.h>
#include <math.h>

#define N_ROWS 100000
#define NF 50
#define NB 16
#define NK 15
#define FPC 1e-4
#define NCOL 25                 // 32-float words per row (800/32)
#define NTILES 3125             // N_ROWS / 32

// ---------------- device scratch (no allocation allowed) -------------------
__device__ unsigned g_comp[(size_t)N_ROWS * NCOL];   // 10 MB row-major mask words
__device__ unsigned g_totp[NCOL * 16];               // packed totals: low16 f=2c, high16 f=2c+1
__device__ unsigned g_badp[NCOL * 16];               // packed bad counts, same layout
__device__ int   g_n1;
__device__ float g_wuse[NF * NB];

// ---------------------------------------------------------------------------
__global__ void zero_kernel() {
    int t = threadIdx.x;
    if (t < NCOL * 16) { g_totp[t] = 0u; g_badp[t] = 0u; }
    if (t == 0) g_n1 = 0;
}

// ---------------------------------------------------------------------------
// Fused compress + count. Warp processes 32-row tiles:
//  phase1: per row, 25 coalesced loads + ballots -> mask words (stored to
//          g_comp for rt, and staged in smem).
//  phase2: lane c grabs its column's 32 words, 32x32 in-register bit
//          transpose, then per-position popc against the y-bitmap.
#define FB_BLOCKS 296
#define FB_THREADS 256
#define FB_WPB (FB_THREADS / 32)
#define FB_WARPS (FB_BLOCKS * FB_WPB)

#define TR_STAGE(J, M)                                              \
    {                                                               \
        _Pragma("unroll")                                           \
        for (int k = 0; k < 32; k++)                                \
            if ((k & (J)) == 0) {                                   \
                unsigned tt = ((w[k] >> (J)) ^ w[k | (J)]) & (M);   \
                w[k] ^= tt << (J);                                  \
                w[k | (J)] ^= tt;                                   \
            }                                                       \
    }

__global__ void __launch_bounds__(FB_THREADS)
fused_kernel(const float* __restrict__ x, const int* __restrict__ y) {
    __shared__ unsigned sm[FB_WPB][32][NCOL + 1];
    const int lane = threadIdx.x & 31;
    const int wlocal = threadIdx.x >> 5;
    const int gwarp = blockIdx.x * FB_WPB + wlocal;
    const int c = (lane < NCOL) ? lane : 0;

    unsigned ctp[16], cbp[16];
    #pragma unroll
    for (int p = 0; p < 16; p++) { ctp[p] = 0u; cbp[p] = 0u; }
    int n1acc = 0;

    for (int t = gwarp; t < NTILES; t += FB_WARPS) {
        const int n0 = t * 32;

        // ---- phase 1: compress 32 rows ----
        for (int r = 0; r < 32; r++) {
            const float* row = x + (size_t)(n0 + r) * (NF * NB);
            unsigned my = 0;
            #pragma unroll
            for (int i = 0; i < NCOL; i++) {
                float v = row[i * 32 + lane];
                unsigned b = __ballot_sync(0xffffffffu, v != 0.f);
                if (lane == i) my = b;
            }
            if (lane < NCOL) {
                sm[wlocal][r][lane] = my;
                g_comp[(size_t)(n0 + r) * NCOL + lane] = my;
            }
        }
        int yv = y[n0 + lane];
        unsigned ym = __ballot_sync(0xffffffffu, yv == 1);
        n1acc += __popc(ym);
        __syncwarp();

        // ---- phase 2: transpose + popcount ----
        unsigned w[32];
        #pragma unroll
        for (int r = 0; r < 32; r++) w[r] = sm[wlocal][r][c];
        __syncwarp();

        TR_STAGE(16, 0x0000FFFFu)
        TR_STAGE(8,  0x00FF00FFu)
        TR_STAGE(4,  0x0F0F0F0Fu)
        TR_STAGE(2,  0x33333333u)
        TR_STAGE(1,  0x55555555u)
        // now w[p] bit r = original word of row r, bit p

        #pragma unroll
        for (int p = 0; p < 16; p++) {
            ctp[p] += (unsigned)__popc(w[p])      + ((unsigned)__popc(w[p + 16])      << 16);
            cbp[p] += (unsigned)__popc(w[p] & ym) + ((unsigned)__popc(w[p + 16] & ym) << 16);
        }
    }

    if (lane < NCOL) {
        #pragma unroll
        for (int p = 0; p < 16; p++) {
            atomicAdd(&g_totp[lane * 16 + p], ctp[p]);
            atomicAdd(&g_badp[lane * 16 + p], cbp[p]);
        }
    }
    if (lane == 0 && n1acc) atomicAdd(&g_n1, n1acc);
}

// ---------------------------------------------------------------------------
// WLS — one warp per feature; shfl-butterfly reductions; solves on all lanes.
__device__ __forceinline__ double red16(double v) {
    #pragma unroll
    for (int o = 8; o > 0; o >>= 1) v += __shfl_xor_sync(0xffffffffu, v, o);
    return v;
}

__global__ void wls_kernel(float* __restrict__ out) {
    const int f = blockIdx.x;
    const int lane = threadIdx.x;

    const int n1 = g_n1;
    const int n0 = N_ROWS - n1;

    float woe_b = 0.f;
    double tot_b = 0.0;
    if (lane < NB) {
        unsigned sh = (unsigned)(f & 1) * 16u;
        int ct = (int)((g_totp[(f >> 1) * 16 + lane] >> sh) & 0xFFFFu);
        int cb = (int)((g_badp[(f >> 1) * 16 + lane] >> sh) & 0xFFFFu);
        int cg = ct - cb;
        woe_b = logf((float)cb / (float)n1 + (float)FPC)
              - logf((float)cg / (float)n0 + (float)FPC);
        tot_b = (double)ct / (double)N_ROWS;
    }

    const bool inK = (lane >= 1 && lane < NB);
    double s = red16(inK ? tot_b : 0.0);
    double pct = inK ? tot_b / s : 0.0;
    double w   = inK ? (double)woe_b : 0.0;

    unsigned nzmask = __ballot_sync(0xffffffffu, inK && pct != 0.0);
    int first = nzmask ? (__ffs(nzmask) - 2) : 0;

    double idxv = 0.0, ind = 0.0;
    if (inK) {
        double v = (double)(lane - first);
        idxv = v > 0.0 ? v : 0.0;
        ind  = (idxv != 0.0) ? 1.0 : 0.0;
    }
    double idx2 = idxv * idxv;

    double s00 = red16(pct * ind * ind);
    double s01 = red16(pct * ind * idxv);
    double s11 = red16(pct * idxv * idxv);
    double r0  = red16(pct * ind * w);
    double r1v = red16(pct * idxv * w);
    double det2 = s00 * s11 - s01 * s01;
    double c10 = (s11 * r0 - s01 * r1v) / det2;
    double c11 = (s00 * r1v - s01 * r0) / det2;
    double fit1 = ind * c10 + idxv * c11;

    double a00 = s00, a01 = s01, a11 = s11;
    double a02 = red16(pct * ind * idx2);
    double a12 = red16(pct * idxv * idx2);
    double a22 = red16(pct * idx2 * idx2);
    double b0 = r0, b1 = r1v;
    double b2 = red16(pct * idx2 * w);
    double m00 = a11 * a22 - a12 * a12;
    double m01 = a01 * a22 - a12 * a02;
    double m02 = a01 * a12 - a11 * a02;
    double det3 = a00 * m00 - a01 * m01 + a02 * m02;
    double c20 = (b0 * m00 - a01 * (b1 * a22 - a12 * b2) + a02 * (b1 * a12 - a11 * b2)) / det3;
    double c21 = (a00 * (b1 * a22 - a12 * b2) - b0 * m01 + a02 * (a01 * b2 - b1 * a02)) / det3;
    double c22 = (a00 * (a11 * b2 - b1 * a12) - a01 * (a01 * b2 - b1 * a02) + b0 * m02) / det3;
    double fit2 = ind * c20 + idxv * c21 + idx2 * c22;

    double mean = red16(w * pct);
    double d0 = w - mean;
    double d1 = fit1 - w;
    double d2 = fit2 - w;
    double sst  = red16(inK ? d0 * d0 * pct : 0.0);
    double sse1 = red16(inK ? d1 * d1 * pct : 0.0);
    double sse2 = red16(inK ? d2 * d2 * pct : 0.0);
    double r1 = 1.0 - sse1 / sst;
    double r2 = 1.0 - sse2 / sst;

    float* out_woe = out + (size_t)N_ROWS * NF;
    float* out_adj = out_woe + NF * NB;

    if (lane < NB) {
        out_woe[f * NB + lane] = woe_b;
        float a;
        if (lane == 0) a = woe_b;
        else a = (float)((fit1 * r1 + fit2 * r2) / (r1 + r2));
        out_adj[f * NB + lane] = a;
        g_wuse[f * NB + lane] = isnan(a) ? 0.0f : a;
    }
}

// ---------------------------------------------------------------------------
// rt: u32 word loads (2 masks each), per-thread constant f-pair, float2 stores.
#define RT_T 800
#define RT_ITER 5
#define RT_BLOCKS 625           // 625 * 800 * 5 = 2,500,000 words

__global__ void __launch_bounds__(RT_T)
rt_kernel(float* __restrict__ out) {
    const int tid = threadIdx.x;
    const int c = tid % NCOL;

    float w0[NB], w1[NB];
    #pragma unroll
    for (int b = 0; b < NB; b++) {
        w0[b] = g_wuse[(2 * c) * NB + b];
        w1[b] = g_wuse[(2 * c + 1) * NB + b];
    }

    const size_t base = (size_t)blockIdx.x * RT_T * RT_ITER;
    float2* out2 = (float2*)out;

    #pragma unroll
    for (int j = 0; j < RT_ITER; j++) {
        size_t wi = base + (size_t)j * RT_T + tid;
        unsigned m = g_comp[wi];

        float s0 = 0.f, s1 = 0.f, s2 = 0.f, s3 = 0.f;
        #pragma unroll
        for (int b = 0; b < NB; b += 4) {
            s0 += ((m >> (b + 0)) & 1u) ? w0[b + 0] : 0.f;
            s1 += ((m >> (b + 1)) & 1u) ? w0[b + 1] : 0.f;
            s2 += ((m >> (b + 2)) & 1u) ? w0[b + 2] : 0.f;
            s3 += ((m >> (b + 3)) & 1u) ? w0[b + 3] : 0.f;
        }
        float t0 = 0.f, t1 = 0.f, t2 = 0.f, t3 = 0.f;
        #pragma unroll
        for (int b = 0; b < NB; b += 4) {
            t0 += ((m >> (16 + b + 0)) & 1u) ? w1[b + 0] : 0.f;
            t1 += ((m >> (16 + b + 1)) & 1u) ? w1[b + 1] : 0.f;
            t2 += ((m >> (16 + b + 2)) & 1u) ? w1[b + 2] : 0.f;
            t3 += ((m >> (16 + b + 3)) & 1u) ? w1[b + 3] : 0.f;
        }
        float2 res;
        res.x = (s0 + s1) + (s2 + s3);
        res.y = (t0 + t1) + (t2 + t3);
        out2[wi] = res;
    }
}

// ---------------------------------------------------------------------------
extern "C" void kernel_launch(void* const* d_in, const int* in_sizes, int n_in,
                              void* d_out, int out_size) {
    const float* x = (const float*)d_in[0];
    const int* y = (const int*)d_in[1];
    float* out = (float*)d_out;

    zero_kernel<<<1, 512>>>();

    fused_kernel<<<FB_BLOCKS, FB_THREADS>>>(x, y);

    wls_kernel<<<NF, 32>>>(out);

    rt_kernel<<<RT_BLOCKS, RT_T>>>(out);
}

// round 6
// speedup vs baseline: 7.3241x; 7.3241x over previous
#include <cuda_runtime.h>
#include <math.h>

#define N_ROWS 100000
#define NF 50
#define NB 16
#define NK 15
#define FPC 1e-4
#define NCOL 25                   // 32-float words per row (800/32)

// ---------------- device scratch (no allocation allowed) -------------------
__device__ unsigned g_comp[(size_t)N_ROWS * NCOL];   // 10 MB row-major mask words
__device__ unsigned g_tot[NF * NB];                  // u32 totals per (f, bin)
__device__ unsigned g_bad[NF * NB];                  // u32 bad counts per (f, bin)
__device__ int   g_n1;
__device__ float g_wuse[NF * NB];

// ---------------------------------------------------------------------------
__global__ void zero_kernel() {
    int t = threadIdx.x;
    if (t < NF * NB) { g_tot[t] = 0u; g_bad[t] = 0u; }
    if (t == 0) g_n1 = 0;
}

// ---------------------------------------------------------------------------
// Fused compress + count. One warp per 32-row tile.
// Per word: ballot IS the mask; every lane holds it, so lane l accumulates
// bit l (feature 2i + (l>=16), bin l%16) into packed 16-bit counter halves.
#define CC_ROWS 32
#define CC_BLOCK 256
#define CC_WPB (CC_BLOCK / 32)
#define CC_TILES (N_ROWS / CC_ROWS)                   // 3125
#define CC_BLOCKS ((CC_TILES + CC_WPB - 1) / CC_WPB)  // 391

__global__ void __launch_bounds__(CC_BLOCK)
compress_count_kernel(const float* __restrict__ x, const int* __restrict__ y) {
    const int lane = threadIdx.x & 31;
    const int tile = blockIdx.x * CC_WPB + (threadIdx.x >> 5);
    if (tile >= CC_TILES) return;
    const int n0 = tile * CC_ROWS;

    const int hi  = lane >> 4;      // which feature within the word
    const int bin = lane & 15;      // bin index

    unsigned tot[13], bad[13];
    #pragma unroll
    for (int j = 0; j < 13; j++) { tot[j] = 0u; bad[j] = 0u; }

    const int yv = y[n0 + lane];
    const unsigned ym = __ballot_sync(0xffffffffu, yv == 1);

    for (int r = 0; r < CC_ROWS; r++) {
        const float* row = x + (size_t)(n0 + r) * (NF * NB);
        const unsigned isbad = (ym >> r) & 1u;
        unsigned my = 0;
        #pragma unroll
        for (int i = 0; i < NCOL; i++) {
            float v = __ldcs(row + i * 32 + lane);
            unsigned b = __ballot_sync(0xffffffffu, v != 0.f);
            if (lane == i) my = b;
            unsigned bit = (b >> lane) & 1u;
            tot[i >> 1] += bit << ((i & 1) * 16);
            bad[i >> 1] += (bit & isbad) << ((i & 1) * 16);
        }
        if (lane < NCOL) g_comp[(size_t)(n0 + r) * NCOL + lane] = my;
    }

    // flush: fixed (f,bin) per (j,half,lane) -> spread atomics
    #pragma unroll
    for (int j = 0; j < 13; j++) {
        int f0 = 4 * j + hi;                       // word i = 2j
        atomicAdd(&g_tot[f0 * NB + bin], tot[j] & 0xFFFFu);
        atomicAdd(&g_bad[f0 * NB + bin], bad[j] & 0xFFFFu);
        if (j < 12) {                              // word i = 2j+1
            int f1 = 4 * j + 2 + hi;
            atomicAdd(&g_tot[f1 * NB + bin], tot[j] >> 16);
            atomicAdd(&g_bad[f1 * NB + bin], bad[j] >> 16);
        }
    }
    if (lane == 0) atomicAdd(&g_n1, __popc(ym));
}

// ---------------------------------------------------------------------------
// WLS — one warp per feature; shfl-butterfly reductions; solves on all lanes.
__device__ __forceinline__ double red16(double v) {
    #pragma unroll
    for (int o = 8; o > 0; o >>= 1) v += __shfl_xor_sync(0xffffffffu, v, o);
    return v;
}

__global__ void wls_kernel(float* __restrict__ out) {
    const int f = blockIdx.x;
    const int lane = threadIdx.x;

    const int n1 = g_n1;
    const int n0 = N_ROWS - n1;

    float woe_b = 0.f;
    double tot_b = 0.0;
    if (lane < NB) {
        int ct = (int)g_tot[f * NB + lane];
        int cb = (int)g_bad[f * NB + lane];
        int cg = ct - cb;
        woe_b = logf((float)cb / (float)n1 + (float)FPC)
              - logf((float)cg / (float)n0 + (float)FPC);
        tot_b = (double)ct / (double)N_ROWS;
    }

    const bool inK = (lane >= 1 && lane < NB);
    double s = red16(inK ? tot_b : 0.0);
    double pct = inK ? tot_b / s : 0.0;
    double w   = inK ? (double)woe_b : 0.0;

    unsigned nzmask = __ballot_sync(0xffffffffu, inK && pct != 0.0);
    int first = nzmask ? (__ffs(nzmask) - 2) : 0;

    double idxv = 0.0, ind = 0.0;
    if (inK) {
        double v = (double)(lane - first);
        idxv = v > 0.0 ? v : 0.0;
        ind  = (idxv != 0.0) ? 1.0 : 0.0;
    }
    double idx2 = idxv * idxv;

    double s00 = red16(pct * ind * ind);
    double s01 = red16(pct * ind * idxv);
    double s11 = red16(pct * idxv * idxv);
    double r0  = red16(pct * ind * w);
    double r1v = red16(pct * idxv * w);
    double det2 = s00 * s11 - s01 * s01;
    double c10 = (s11 * r0 - s01 * r1v) / det2;
    double c11 = (s00 * r1v - s01 * r0) / det2;
    double fit1 = ind * c10 + idxv * c11;

    double a00 = s00, a01 = s01, a11 = s11;
    double a02 = red16(pct * ind * idx2);
    double a12 = red16(pct * idxv * idx2);
    double a22 = red16(pct * idx2 * idx2);
    double b0 = r0, b1 = r1v;
    double b2 = red16(pct * idx2 * w);
    double m00 = a11 * a22 - a12 * a12;
    double m01 = a01 * a22 - a12 * a02;
    double m02 = a01 * a12 - a11 * a02;
    double det3 = a00 * m00 - a01 * m01 + a02 * m02;
    double c20 = (b0 * m00 - a01 * (b1 * a22 - a12 * b2) + a02 * (b1 * a12 - a11 * b2)) / det3;
    double c21 = (a00 * (b1 * a22 - a12 * b2) - b0 * m01 + a02 * (a01 * b2 - b1 * a02)) / det3;
    double c22 = (a00 * (a11 * b2 - b1 * a12) - a01 * (a01 * b2 - b1 * a02) + b0 * m02) / det3;
    double fit2 = ind * c20 + idxv * c21 + idx2 * c22;

    double mean = red16(w * pct);
    double d0 = w - mean;
    double d1 = fit1 - w;
    double d2 = fit2 - w;
    double sst  = red16(inK ? d0 * d0 * pct : 0.0);
    double sse1 = red16(inK ? d1 * d1 * pct : 0.0);
    double sse2 = red16(inK ? d2 * d2 * pct : 0.0);
    double r1 = 1.0 - sse1 / sst;
    double r2 = 1.0 - sse2 / sst;

    float* out_woe = out + (size_t)N_ROWS * NF;
    float* out_adj = out_woe + NF * NB;

    if (lane < NB) {
        out_woe[f * NB + lane] = woe_b;
        float a;
        if (lane == 0) a = woe_b;
        else a = (float)((fit1 * r1 + fit2 * r2) / (r1 + r2));
        out_adj[f * NB + lane] = a;
        g_wuse[f * NB + lane] = isnan(a) ? 0.0f : a;
    }
}

// ---------------------------------------------------------------------------
// rt: exact R3 build (measured 19.7us): fixed-f-per-thread, 16-register LUT,
// 16 predicated adds per u16 mask, coalesced I/O.
#define RT_THREADS 800
#define RT_RPB 400
#define RT_BLOCKS (N_ROWS / RT_RPB)      // 250
#define RT_ITERS (RT_RPB / 16)           // 25 masks per thread

__global__ void __launch_bounds__(RT_THREADS)
rt_kernel(float* __restrict__ out) {
    const int tid = threadIdx.x;
    const int f = tid % NF;
    const size_t base = (size_t)blockIdx.x * RT_RPB * NF;

    float wv[NB];
    #pragma unroll
    for (int b = 0; b < NB; b++) wv[b] = g_wuse[f * NB + b];

    const unsigned short* comp = (const unsigned short*)g_comp;

    #pragma unroll 5
    for (int i = 0; i < RT_ITERS; i++) {
        size_t p = base + (size_t)i * RT_THREADS + tid;
        unsigned m = comp[p];
        float s0 = 0.f, s1 = 0.f, s2 = 0.f, s3 = 0.f;
        #pragma unroll
        for (int b = 0; b < NB; b += 4) {
            s0 += ((m >> (b + 0)) & 1u) ? wv[b + 0] : 0.f;
            s1 += ((m >> (b + 1)) & 1u) ? wv[b + 1] : 0.f;
            s2 += ((m >> (b + 2)) & 1u) ? wv[b + 2] : 0.f;
            s3 += ((m >> (b + 3)) & 1u) ? wv[b + 3] : 0.f;
        }
        out[p] = (s0 + s1) + (s2 + s3);
    }
}

// ---------------------------------------------------------------------------
extern "C" void kernel_launch(void* const* d_in, const int* in_sizes, int n_in,
                              void* d_out, int out_size) {
    const float* x = (const float*)d_in[0];
    const int* y = (const int*)d_in[1];
    float* out = (float*)d_out;

    zero_kernel<<<1, NF * NB>>>();

    compress_count_kernel<<<CC_BLOCKS, CC_BLOCK>>>(x, y);

    wls_kernel<<<NF, 32>>>(out);

    rt_kernel<<<RT_BLOCKS, RT_THREADS>>>(out);
}